// round 2
// baseline (speedup 1.0000x reference)
#include <cuda_runtime.h>
#include <math.h>

// Problem constants
#define BB 4096
#define PP 16
#define DD 512
#define FF 2048
#define EE 8

// -------- scratch (device globals; no allocations) --------
__device__ int   g_counts[EE];
__device__ int   g_rows[EE * BB];
__device__ float g_gates[EE * BB];

// -------- zero the per-expert counters --------
__global__ void zero_counts_kernel() {
    if (threadIdx.x < EE) g_counts[threadIdx.x] = 0;
}

// -------- router: noisy top-2 + 2-way softmax, scatter to expert lists --------
__global__ void router_kernel(const float* __restrict__ aff,
                              const float* __restrict__ noise) {
    int b = blockIdx.x * blockDim.x + threadIdx.x;
    if (b >= BB) return;

    float v[EE];
#pragma unroll
    for (int e = 0; e < EE; ++e) {
        float a  = aff[b * EE + e];
        // stable softplus = logaddexp(a, 0)
        float sp = (a > 0.f) ? (a + log1pf(expf(-a))) : log1pf(expf(a));
        v[e] = a + noise[b * EE + e] * sp;
    }

    // top-1 (first max on ties, matching jax top_k)
    int i0 = 0; float v0 = v[0];
#pragma unroll
    for (int e = 1; e < EE; ++e) if (v[e] > v0) { v0 = v[e]; i0 = e; }
    // top-2
    int i1 = -1; float v1 = -INFINITY;
#pragma unroll
    for (int e = 0; e < EE; ++e) if (e != i0 && v[e] > v1) { v1 = v[e]; i1 = e; }

    // softmax over {v0, v1} (others are -inf -> exactly 0 gate)
    float ex  = expf(v1 - v0);
    float inv = 1.f / (1.f + ex);
    float g0  = inv;
    float g1  = ex * inv;

    int p0 = atomicAdd(&g_counts[i0], 1);
    g_rows[i0 * BB + p0]  = b;
    g_gates[i0 * BB + p0] = g0;
    int p1 = atomicAdd(&g_counts[i1], 1);
    g_rows[i1 * BB + p1]  = b;
    g_gates[i1 * BB + p1] = g1;
}

// -------- fused expert FFN --------
// Per CTA: one expert, 2 gathered b-rows = 32 token-patches, full D output.
// Smem: Xs [32][512] (64KB) | hs [32][128] (16KB) | ws shared stage (64KB)
// Loop over F in blocks of 128:
//   GEMM1 (Xs @ W1-block, W1 staged 64x128) -> gelu -> hs (warp-private rows)
//   GEMM2 (hs @ W2-block, W2 staged 32x512 per sub-chunk) -> acc[32][512] in regs
// Epilogue: atomicAdd(out, gate * (acc + b2))

#define SMEM_FLOATS (32 * 512 + 32 * 128 + 16384)
#define SMEM_BYTES  (SMEM_FLOATS * 4)

__global__ __launch_bounds__(256)
void ffn_kernel(const float* __restrict__ X,
                const float* __restrict__ W1,
                const float* __restrict__ b1,
                const float* __restrict__ W2,
                const float* __restrict__ b2,
                float* __restrict__ out) {
    int e    = blockIdx.y;
    int cnt  = g_counts[e];
    int tile = blockIdx.x;
    if (tile * 2 >= cnt) return;   // uniform across CTA

    int   ent0  = tile * 2;
    int   b0    = g_rows[e * BB + ent0];
    float gate0 = g_gates[e * BB + ent0];
    int   b1i   = b0;
    float gate1 = 0.f;               // duplicate row, zero gate -> adds exactly 0
    if (ent0 + 1 < cnt) {
        b1i   = g_rows[e * BB + ent0 + 1];
        gate1 = g_gates[e * BB + ent0 + 1];
    }

    extern __shared__ float sm[];
    float* Xs = sm;                  // [32][512]
    float* hs = sm + 32 * 512;       // [32][128]
    float* ws = hs + 32 * 128;       // [64][128] for W1 / [32][512] for W2

    int tid = threadIdx.x;

    // stage X (fp32, coalesced float4)
    const float* xp0 = X + (size_t)b0  * PP * DD;
    const float* xp1 = X + (size_t)b1i * PP * DD;
    for (int i = tid; i < (32 * 512) / 4; i += 256) {
        int idx = i * 4;
        int tok = idx >> 9, d = idx & 511;
        const float* src = (tok < 16) ? (xp0 + tok * DD + d)
                                      : (xp1 + (tok - 16) * DD + d);
        *(float4*)(Xs + idx) = *(const float4*)src;
    }

    const float* W1e = W1 + (size_t)e * DD * FF;
    const float* W2e = W2 + (size_t)e * FF * DD;
    const float* b1e = b1 + e * FF;
    const float* b2e = b2 + e * DD;

    int tg = (tid >> 5) * 4;   // token base (warp-major): 0..28
    int fc = (tid & 31) * 4;   // f-col base within 128-block
    int dq = (tid & 31) * 4;   // d-col base for GEMM2 (plus 128*k)

    float acc[4][16];
#pragma unroll
    for (int i = 0; i < 4; ++i)
#pragma unroll
        for (int j = 0; j < 16; ++j) acc[i][j] = 0.f;

    for (int fb = 0; fb < FF; fb += 128) {
        // ---- GEMM1: a1[tok 4][f 4] = Xs[32,512] @ W1[:, fb:fb+128] ----
        float a1[4][4];
#pragma unroll
        for (int i = 0; i < 4; ++i)
#pragma unroll
            for (int j = 0; j < 4; ++j) a1[i][j] = 0.f;

        for (int dc = 0; dc < DD; dc += 64) {
            __syncthreads();  // prior ws users done (also orders Xs load on 1st iter)
            for (int i = tid; i < (64 * 128) / 4; i += 256) {
                int idx = i * 4; int r = idx >> 7, c = idx & 127;
                *(float4*)(ws + idx) =
                    *(const float4*)(W1e + (size_t)(dc + r) * FF + fb + c);
            }
            __syncthreads();

            const float* xr0 = Xs + (tg + 0) * 512 + dc;
            const float* xr1 = Xs + (tg + 1) * 512 + dc;
            const float* xr2 = Xs + (tg + 2) * 512 + dc;
            const float* xr3 = Xs + (tg + 3) * 512 + dc;
#pragma unroll 4
            for (int d = 0; d < 64; ++d) {
                float4 w = *(const float4*)(ws + d * 128 + fc);  // LDS.128, conflict-free
                float x0 = xr0[d], x1 = xr1[d], x2 = xr2[d], x3 = xr3[d];  // broadcast
                a1[0][0] += x0 * w.x; a1[0][1] += x0 * w.y; a1[0][2] += x0 * w.z; a1[0][3] += x0 * w.w;
                a1[1][0] += x1 * w.x; a1[1][1] += x1 * w.y; a1[1][2] += x1 * w.z; a1[1][3] += x1 * w.w;
                a1[2][0] += x2 * w.x; a1[2][1] += x2 * w.y; a1[2][2] += x2 * w.z; a1[2][3] += x2 * w.w;
                a1[3][0] += x3 * w.x; a1[3][1] += x3 * w.y; a1[3][2] += x3 * w.z; a1[3][3] += x3 * w.w;
            }
        }

        // ---- bias + tanh-gelu (jax default approximate=True), store to hs ----
        // hs rows tg..tg+3 are written and later read only by this warp.
#pragma unroll
        for (int i = 0; i < 4; ++i)
#pragma unroll
            for (int j = 0; j < 4; ++j) {
                float t = a1[i][j] + b1e[fb + fc + j];
                float c = t + 0.044715f * t * t * t;
                float g = 0.5f * t * (1.f + tanhf(0.7978845608028654f * c));
                hs[(tg + i) * 128 + fc + j] = g;
            }

        // ---- GEMM2: acc[32,512] += hs[32,128-block] @ W2[fb-block, :] ----
        for (int fs = 0; fs < 128; fs += 32) {
            __syncthreads();  // ws reuse; also orders hs writes before cross-lane reads
            for (int i = tid; i < (32 * 512) / 4; i += 256) {
                int idx = i * 4; int r = idx >> 9, c = idx & 511;
                *(float4*)(ws + idx) =
                    *(const float4*)(W2e + (size_t)(fb + fs + r) * DD + c);
            }
            __syncthreads();

#pragma unroll 2
            for (int f = 0; f < 32; ++f) {
                const float* wr = ws + f * 512 + dq;
                float h0 = hs[(tg + 0) * 128 + fs + f];
                float h1 = hs[(tg + 1) * 128 + fs + f];
                float h2 = hs[(tg + 2) * 128 + fs + f];
                float h3 = hs[(tg + 3) * 128 + fs + f];
#pragma unroll
                for (int k = 0; k < 4; ++k) {
                    float4 w = *(const float4*)(wr + 128 * k);   // LDS.128, conflict-free
                    acc[0][k * 4 + 0] += h0 * w.x; acc[0][k * 4 + 1] += h0 * w.y;
                    acc[0][k * 4 + 2] += h0 * w.z; acc[0][k * 4 + 3] += h0 * w.w;
                    acc[1][k * 4 + 0] += h1 * w.x; acc[1][k * 4 + 1] += h1 * w.y;
                    acc[1][k * 4 + 2] += h1 * w.z; acc[1][k * 4 + 3] += h1 * w.w;
                    acc[2][k * 4 + 0] += h2 * w.x; acc[2][k * 4 + 1] += h2 * w.y;
                    acc[2][k * 4 + 2] += h2 * w.z; acc[2][k * 4 + 3] += h2 * w.w;
                    acc[3][k * 4 + 0] += h3 * w.x; acc[3][k * 4 + 1] += h3 * w.y;
                    acc[3][k * 4 + 2] += h3 * w.z; acc[3][k * 4 + 3] += h3 * w.w;
                }
            }
        }
    }

    // ---- epilogue: out += gate * (acc + b2) ----
#pragma unroll
    for (int i = 0; i < 4; ++i) {
        int tok = tg + i;
        float g  = (tok < 16) ? gate0 : gate1;
        int   bb = (tok < 16) ? b0 : b1i;
        int   p  = tok & 15;
        float* op = out + ((size_t)bb * PP + p) * DD;
#pragma unroll
        for (int k = 0; k < 4; ++k)
#pragma unroll
            for (int j = 0; j < 4; ++j) {
                int d = dq + 128 * k + j;
                atomicAdd(op + d, g * (acc[i][k * 4 + j] + b2e[d]));
            }
    }
}

// -------- launch --------
extern "C" void kernel_launch(void* const* d_in, const int* in_sizes, int n_in,
                              void* d_out, int out_size) {
    const float* patch_x  = (const float*)d_in[0];
    // d_in[1] = patch_embedding (shape-only in reference; unused)
    const float* affinity = (const float*)d_in[2];
    const float* noise    = (const float*)d_in[3];
    const float* W1       = (const float*)d_in[4];
    const float* b1       = (const float*)d_in[5];
    const float* W2       = (const float*)d_in[6];
    const float* b2       = (const float*)d_in[7];
    float* out = (float*)d_out;

    cudaMemsetAsync(out, 0, (size_t)out_size * sizeof(float));
    zero_counts_kernel<<<1, 32>>>();
    router_kernel<<<BB / 256, 256>>>(affinity, noise);

    cudaFuncSetAttribute(ffn_kernel,
                         cudaFuncAttributeMaxDynamicSharedMemorySize, SMEM_BYTES);
    dim3 grid(BB / 2, EE);   // covers worst case (all rows on one expert)
    ffn_kernel<<<grid, 256, SMEM_BYTES>>>(patch_x, W1, b1, W2, b2, out);
}

// round 3
// speedup vs baseline: 1.0000x; 1.0000x over previous
#include <cuda_runtime.h>
#include <math.h>

// Problem constants
#define BB 4096
#define PP 16
#define DD 512
#define FF 2048
#define EE 8

// -------- scratch (device globals; no allocations) --------
__device__ int   g_counts[EE];
__device__ int   g_rows[EE * BB];
__device__ float g_gates[EE * BB];

// -------- zero the per-expert counters --------
__global__ void zero_counts_kernel() {
    if (threadIdx.x < EE) g_counts[threadIdx.x] = 0;
}

// -------- router: noisy top-2 + 2-way softmax, scatter to expert lists --------
__global__ void router_kernel(const float* __restrict__ aff,
                              const float* __restrict__ noise) {
    int b = blockIdx.x * blockDim.x + threadIdx.x;
    if (b >= BB) return;

    float v[EE];
#pragma unroll
    for (int e = 0; e < EE; ++e) {
        float a  = aff[b * EE + e];
        // stable softplus = logaddexp(a, 0)
        float sp = (a > 0.f) ? (a + log1pf(expf(-a))) : log1pf(expf(a));
        v[e] = a + noise[b * EE + e] * sp;
    }

    // top-1 (first max on ties, matching jax top_k)
    int i0 = 0; float v0 = v[0];
#pragma unroll
    for (int e = 1; e < EE; ++e) if (v[e] > v0) { v0 = v[e]; i0 = e; }
    // top-2
    int i1 = -1; float v1 = -INFINITY;
#pragma unroll
    for (int e = 0; e < EE; ++e) if (e != i0 && v[e] > v1) { v1 = v[e]; i1 = e; }

    // softmax over {v0, v1} (others are -inf -> exactly 0 gate)
    float ex  = expf(v1 - v0);
    float inv = 1.f / (1.f + ex);
    float g0  = inv;
    float g1  = ex * inv;

    int p0 = atomicAdd(&g_counts[i0], 1);
    g_rows[i0 * BB + p0]  = b;
    g_gates[i0 * BB + p0] = g0;
    int p1 = atomicAdd(&g_counts[i1], 1);
    g_rows[i1 * BB + p1]  = b;
    g_gates[i1 * BB + p1] = g1;
}

// -------- fused expert FFN --------
// Per CTA: one expert, 2 gathered b-rows = 32 token-patches, full D output.
// Smem: Xs [32][512] (64KB) | hs [32][128] (16KB) | ws shared stage (64KB)
// Loop over F in blocks of 128:
//   GEMM1 (Xs @ W1-block, W1 staged 64x128) -> gelu -> hs (warp-private rows)
//   GEMM2 (hs @ W2-block, W2 staged 32x512 per sub-chunk) -> acc[32][512] in regs
// Epilogue: atomicAdd(out, gate * (acc + b2))

#define SMEM_FLOATS (32 * 512 + 32 * 128 + 16384)
#define SMEM_BYTES  (SMEM_FLOATS * 4)

__global__ __launch_bounds__(256)
void ffn_kernel(const float* __restrict__ X,
                const float* __restrict__ W1,
                const float* __restrict__ b1,
                const float* __restrict__ W2,
                const float* __restrict__ b2,
                float* __restrict__ out) {
    int e    = blockIdx.y;
    int cnt  = g_counts[e];
    int tile = blockIdx.x;
    if (tile * 2 >= cnt) return;   // uniform across CTA

    int   ent0  = tile * 2;
    int   b0    = g_rows[e * BB + ent0];
    float gate0 = g_gates[e * BB + ent0];
    int   b1i   = b0;
    float gate1 = 0.f;               // duplicate row, zero gate -> adds exactly 0
    if (ent0 + 1 < cnt) {
        b1i   = g_rows[e * BB + ent0 + 1];
        gate1 = g_gates[e * BB + ent0 + 1];
    }

    extern __shared__ float sm[];
    float* Xs = sm;                  // [32][512]
    float* hs = sm + 32 * 512;       // [32][128]
    float* ws = hs + 32 * 128;       // [64][128] for W1 / [32][512] for W2

    int tid = threadIdx.x;

    // stage X (fp32, coalesced float4)
    const float* xp0 = X + (size_t)b0  * PP * DD;
    const float* xp1 = X + (size_t)b1i * PP * DD;
    for (int i = tid; i < (32 * 512) / 4; i += 256) {
        int idx = i * 4;
        int tok = idx >> 9, d = idx & 511;
        const float* src = (tok < 16) ? (xp0 + tok * DD + d)
                                      : (xp1 + (tok - 16) * DD + d);
        *(float4*)(Xs + idx) = *(const float4*)src;
    }

    const float* W1e = W1 + (size_t)e * DD * FF;
    const float* W2e = W2 + (size_t)e * FF * DD;
    const float* b1e = b1 + e * FF;
    const float* b2e = b2 + e * DD;

    int tg = (tid >> 5) * 4;   // token base (warp-major): 0..28
    int fc = (tid & 31) * 4;   // f-col base within 128-block
    int dq = (tid & 31) * 4;   // d-col base for GEMM2 (plus 128*k)

    float acc[4][16];
#pragma unroll
    for (int i = 0; i < 4; ++i)
#pragma unroll
        for (int j = 0; j < 16; ++j) acc[i][j] = 0.f;

    for (int fb = 0; fb < FF; fb += 128) {
        // ---- GEMM1: a1[tok 4][f 4] = Xs[32,512] @ W1[:, fb:fb+128] ----
        float a1[4][4];
#pragma unroll
        for (int i = 0; i < 4; ++i)
#pragma unroll
            for (int j = 0; j < 4; ++j) a1[i][j] = 0.f;

        for (int dc = 0; dc < DD; dc += 64) {
            __syncthreads();  // prior ws users done (also orders Xs load on 1st iter)
            for (int i = tid; i < (64 * 128) / 4; i += 256) {
                int idx = i * 4; int r = idx >> 7, c = idx & 127;
                *(float4*)(ws + idx) =
                    *(const float4*)(W1e + (size_t)(dc + r) * FF + fb + c);
            }
            __syncthreads();

            const float* xr0 = Xs + (tg + 0) * 512 + dc;
            const float* xr1 = Xs + (tg + 1) * 512 + dc;
            const float* xr2 = Xs + (tg + 2) * 512 + dc;
            const float* xr3 = Xs + (tg + 3) * 512 + dc;
#pragma unroll 4
            for (int d = 0; d < 64; ++d) {
                float4 w = *(const float4*)(ws + d * 128 + fc);  // LDS.128, conflict-free
                float x0 = xr0[d], x1 = xr1[d], x2 = xr2[d], x3 = xr3[d];  // broadcast
                a1[0][0] += x0 * w.x; a1[0][1] += x0 * w.y; a1[0][2] += x0 * w.z; a1[0][3] += x0 * w.w;
                a1[1][0] += x1 * w.x; a1[1][1] += x1 * w.y; a1[1][2] += x1 * w.z; a1[1][3] += x1 * w.w;
                a1[2][0] += x2 * w.x; a1[2][1] += x2 * w.y; a1[2][2] += x2 * w.z; a1[2][3] += x2 * w.w;
                a1[3][0] += x3 * w.x; a1[3][1] += x3 * w.y; a1[3][2] += x3 * w.z; a1[3][3] += x3 * w.w;
            }
        }

        // ---- bias + tanh-gelu (jax default approximate=True), store to hs ----
        // hs rows tg..tg+3 are written and later read only by this warp.
#pragma unroll
        for (int i = 0; i < 4; ++i)
#pragma unroll
            for (int j = 0; j < 4; ++j) {
                float t = a1[i][j] + b1e[fb + fc + j];
                float c = t + 0.044715f * t * t * t;
                float g = 0.5f * t * (1.f + tanhf(0.7978845608028654f * c));
                hs[(tg + i) * 128 + fc + j] = g;
            }

        // ---- GEMM2: acc[32,512] += hs[32,128-block] @ W2[fb-block, :] ----
        for (int fs = 0; fs < 128; fs += 32) {
            __syncthreads();  // ws reuse; also orders hs writes before cross-lane reads
            for (int i = tid; i < (32 * 512) / 4; i += 256) {
                int idx = i * 4; int r = idx >> 9, c = idx & 511;
                *(float4*)(ws + idx) =
                    *(const float4*)(W2e + (size_t)(fb + fs + r) * DD + c);
            }
            __syncthreads();

#pragma unroll 2
            for (int f = 0; f < 32; ++f) {
                const float* wr = ws + f * 512 + dq;
                float h0 = hs[(tg + 0) * 128 + fs + f];
                float h1 = hs[(tg + 1) * 128 + fs + f];
                float h2 = hs[(tg + 2) * 128 + fs + f];
                float h3 = hs[(tg + 3) * 128 + fs + f];
#pragma unroll
                for (int k = 0; k < 4; ++k) {
                    float4 w = *(const float4*)(wr + 128 * k);   // LDS.128, conflict-free
                    acc[0][k * 4 + 0] += h0 * w.x; acc[0][k * 4 + 1] += h0 * w.y;
                    acc[0][k * 4 + 2] += h0 * w.z; acc[0][k * 4 + 3] += h0 * w.w;
                    acc[1][k * 4 + 0] += h1 * w.x; acc[1][k * 4 + 1] += h1 * w.y;
                    acc[1][k * 4 + 2] += h1 * w.z; acc[1][k * 4 + 3] += h1 * w.w;
                    acc[2][k * 4 + 0] += h2 * w.x; acc[2][k * 4 + 1] += h2 * w.y;
                    acc[2][k * 4 + 2] += h2 * w.z; acc[2][k * 4 + 3] += h2 * w.w;
                    acc[3][k * 4 + 0] += h3 * w.x; acc[3][k * 4 + 1] += h3 * w.y;
                    acc[3][k * 4 + 2] += h3 * w.z; acc[3][k * 4 + 3] += h3 * w.w;
                }
            }
        }
    }

    // ---- epilogue: out += gate * (acc + b2) ----
#pragma unroll
    for (int i = 0; i < 4; ++i) {
        int tok = tg + i;
        float g  = (tok < 16) ? gate0 : gate1;
        int   bb = (tok < 16) ? b0 : b1i;
        int   p  = tok & 15;
        float* op = out + ((size_t)bb * PP + p) * DD;
#pragma unroll
        for (int k = 0; k < 4; ++k)
#pragma unroll
            for (int j = 0; j < 4; ++j) {
                int d = dq + 128 * k + j;
                atomicAdd(op + d, g * (acc[i][k * 4 + j] + b2e[d]));
            }
    }
}

// -------- launch --------
extern "C" void kernel_launch(void* const* d_in, const int* in_sizes, int n_in,
                              void* d_out, int out_size) {
    const float* patch_x  = (const float*)d_in[0];
    // d_in[1] = patch_embedding (shape-only in reference; unused)
    const float* affinity = (const float*)d_in[2];
    const float* noise    = (const float*)d_in[3];
    const float* W1       = (const float*)d_in[4];
    const float* b1       = (const float*)d_in[5];
    const float* W2       = (const float*)d_in[6];
    const float* b2       = (const float*)d_in[7];
    float* out = (float*)d_out;

    cudaMemsetAsync(out, 0, (size_t)out_size * sizeof(float));
    zero_counts_kernel<<<1, 32>>>();
    router_kernel<<<BB / 256, 256>>>(affinity, noise);

    cudaFuncSetAttribute(ffn_kernel,
                         cudaFuncAttributeMaxDynamicSharedMemorySize, SMEM_BYTES);
    dim3 grid(BB / 2, EE);   // covers worst case (all rows on one expert)
    ffn_kernel<<<grid, 256, SMEM_BYTES>>>(patch_x, W1, b1, W2, b2, out);
}